// round 15
// baseline (speedup 1.0000x reference)
#include <cuda_runtime.h>
#include <cuda_fp16.h>
#include <cfloat>
#include <math.h>
#include <cstdint>
#include <mma.h>

using namespace nvcuda;

// Problem constants
#define NN   20000
#define NE   320000
#define HC   512
#define NH   4
#define OC   128
#define KDIM 512
#define NDIM 512
#define ETOT (NE + NN)   // 340000 (divisible by 4; NE divisible by 4)

// -------- scratch --------
__device__ __half g_xh[(size_t)NN * KDIM];    // x, fp16
__device__ __half g_wh[(size_t)KDIM * NDIM];  // W, fp16
__device__ __half g_xlh[(size_t)NN * HC];     // projected features, fp16
__device__ __align__(16) float g_as[NN * NH];
__device__ __align__(16) float g_ad[NN * NH];
__device__ __align__(16) float g_den[NN * NH];
__device__ __align__(16) float g_ew[(size_t)ETOT * NH];  // cached exp per (edge, head)

// ---------------- fp16 pre-conversion of x and W (16 floats/thread) -----
__global__ void k_cvt(const float* __restrict__ x, const float* __restrict__ W) {
    const int totx16 = NN * KDIM / 16;     // 640,000
    const int totw16 = KDIM * NDIM / 16;   //  16,384
    int i = blockIdx.x * blockDim.x + threadIdx.x;
    const float4* src;
    uint4* dst;
    int j;
    if (i < totx16)               { src = (const float4*)x; dst = (uint4*)g_xh; j = i; }
    else if (i < totx16 + totw16) { src = (const float4*)W; dst = (uint4*)g_wh; j = i - totx16; }
    else return;
    float4 v0 = src[4 * j];
    float4 v1 = src[4 * j + 1];
    float4 v2 = src[4 * j + 2];
    float4 v3 = src[4 * j + 3];
    union { uint4 u; __half2 h[4]; } p0, p1;
    p0.h[0] = __floats2half2_rn(v0.x, v0.y);
    p0.h[1] = __floats2half2_rn(v0.z, v0.w);
    p0.h[2] = __floats2half2_rn(v1.x, v1.y);
    p0.h[3] = __floats2half2_rn(v1.z, v1.w);
    p1.h[0] = __floats2half2_rn(v2.x, v2.y);
    p1.h[1] = __floats2half2_rn(v2.z, v2.w);
    p1.h[2] = __floats2half2_rn(v3.x, v3.y);
    p1.h[3] = __floats2half2_rn(v3.z, v3.w);
    dst[2 * j]     = p0.u;
    dst[2 * j + 1] = p1.u;
}

// ---------------- GEMM (fp16 wmma 16x16x16) + fused epilogue -------------
#define BLK_K  64
#define LDA_H  72
#define LDB_H  136
#define A_HALFS (128 * LDA_H)
#define B_HALFS (BLK_K * LDB_H)
#define STAGE_HALFS (A_HALFS + B_HALFS)
#define NSTAGE 3
#define GEMM_SMEM (NSTAGE * STAGE_HALFS * 2)
#define LDC 132

__device__ __forceinline__ uint32_t smem_u32(const void* p) {
    uint32_t a;
    asm("{ .reg .u64 t; cvta.to.shared.u64 t, %1; cvt.u32.u64 %0, t; }" : "=r"(a) : "l"(p));
    return a;
}

__global__ __launch_bounds__(256) void k_gemm_tc(const float* __restrict__ att_src,
                                                 const float* __restrict__ att_dst) {
    extern __shared__ __half smemh[];
    __half* As = smemh;
    __half* Bs = smemh + NSTAGE * A_HALFS;

    const int tid = threadIdx.x;
    const int warpId = tid >> 5;
    const int lane = tid & 31;
    const int warpM = warpId & 3;
    const int warpN = warpId >> 2;
    const int m0 = blockIdx.y * 128;
    const int n0 = blockIdx.x * 128;

    const uint32_t sA = smem_u32(As);
    const uint32_t sB = smem_u32(Bs);

    auto load_stage = [&](int kc, int buf) {
        const int k0 = kc * BLK_K;
        #pragma unroll
        for (int it = 0; it < 4; it++) {
            int id = tid + it * 256;
            int r = id >> 3, q = id & 7;
            int grow = m0 + r;
            const __half* gp = g_xh + (size_t)(grow < NN ? grow : 0) * KDIM + k0 + q * 8;
            int sz = (grow < NN) ? 16 : 0;
            uint32_t so = sA + (buf * A_HALFS + r * LDA_H + q * 8) * 2;
            asm volatile("cp.async.cg.shared.global [%0], [%1], 16, %2;"
                         :: "r"(so), "l"(gp), "r"(sz));
        }
        #pragma unroll
        for (int it = 0; it < 4; it++) {
            int id = tid + it * 256;
            int r = id >> 4, q = id & 15;
            const __half* gp = g_wh + (size_t)(k0 + r) * NDIM + n0 + q * 8;
            uint32_t so = sB + (buf * B_HALFS + r * LDB_H + q * 8) * 2;
            asm volatile("cp.async.cg.shared.global [%0], [%1], 16;"
                         :: "r"(so), "l"(gp));
        }
        asm volatile("cp.async.commit_group;" ::: "memory");
    };

    wmma::fragment<wmma::accumulator, 16, 16, 16, float> acc[2][4];
    #pragma unroll
    for (int i = 0; i < 2; i++)
        #pragma unroll
        for (int j = 0; j < 4; j++) wmma::fill_fragment(acc[i][j], 0.f);

    load_stage(0, 0);
    load_stage(1, 1);

    const int NCHUNK = KDIM / BLK_K;   // 8
    for (int kc = 0; kc < NCHUNK; kc++) {
        const int buf = kc % NSTAGE;
        if (kc + 1 < NCHUNK)
            asm volatile("cp.async.wait_group 1;" ::: "memory");
        else
            asm volatile("cp.async.wait_group 0;" ::: "memory");
        __syncthreads();
        if (kc + 2 < NCHUNK) load_stage(kc + 2, (kc + 2) % NSTAGE);

        const __half* Ab = As + buf * A_HALFS + warpM * 32 * LDA_H;
        const __half* Bb = Bs + buf * B_HALFS + warpN * 64;
        #pragma unroll
        for (int ks = 0; ks < BLK_K / 16; ks++) {
            wmma::fragment<wmma::matrix_a, 16, 16, 16, __half, wmma::row_major> af[2];
            wmma::fragment<wmma::matrix_b, 16, 16, 16, __half, wmma::row_major> bf[4];
            #pragma unroll
            for (int mt = 0; mt < 2; mt++)
                wmma::load_matrix_sync(af[mt], Ab + mt * 16 * LDA_H + ks * 16, LDA_H);
            #pragma unroll
            for (int nt = 0; nt < 4; nt++)
                wmma::load_matrix_sync(bf[nt], Bb + ks * 16 * LDB_H + nt * 16, LDB_H);
            #pragma unroll
            for (int mt = 0; mt < 2; mt++)
                #pragma unroll
                for (int nt = 0; nt < 4; nt++)
                    wmma::mma_sync(acc[mt][nt], af[mt], bf[nt], acc[mt][nt]);
        }
    }

    // -------- fused epilogue: attn halves + fp16 store --------
    __syncthreads();
    float* Cs = (float*)smemh;
    #pragma unroll
    for (int mt = 0; mt < 2; mt++)
        #pragma unroll
        for (int nt = 0; nt < 4; nt++)
            wmma::store_matrix_sync(Cs + (warpM * 32 + mt * 16) * LDC + warpN * 64 + nt * 16,
                                    acc[mt][nt], LDC, wmma::mem_row_major);
    __syncthreads();

    const int h = blockIdx.x;
    float4 sv = *(const float4*)(att_src + h * OC + lane * 4);
    float4 dv = *(const float4*)(att_dst + h * OC + lane * 4);

    #pragma unroll
    for (int r = 0; r < 16; r++) {
        int lrow = warpId * 16 + r;
        int grow = m0 + lrow;
        float4 v = *(const float4*)(Cs + lrow * LDC + lane * 4);
        float ss = v.x * sv.x + v.y * sv.y + v.z * sv.z + v.w * sv.w;
        float dd = v.x * dv.x + v.y * dv.y + v.z * dv.z + v.w * dv.w;
        #pragma unroll
        for (int o = 16; o; o >>= 1) {
            ss += __shfl_xor_sync(0xFFFFFFFFu, ss, o);
            dd += __shfl_xor_sync(0xFFFFFFFFu, dd, o);
        }
        if (grow < NN) {
            union { uint2 u; __half2 hh[2]; } pk;
            pk.hh[0] = __floats2half2_rn(v.x, v.y);
            pk.hh[1] = __floats2half2_rn(v.z, v.w);
            *(uint2*)(g_xlh + (size_t)grow * HC + h * OC + lane * 4) = pk.u;
            if (lane == 0) {
                g_as[grow * NH + h] = ss;
                g_ad[grow * NH + h] = dd;
            }
        }
    }
}

__device__ __forceinline__ float leaky(float a) { return a > 0.f ? a : 0.2f * a; }

// ---------------- segment sum of exp: 4 edges/thread, caches exps -------
__global__ void k_edge_sum(const int* __restrict__ ei) {
    int t = blockIdx.x * blockDim.x + threadIdx.x;
    if (t >= ETOT / 4) return;
    const int e0 = 4 * t;

    int s[4], d[4];
    if (e0 < NE) {   // NE % 4 == 0: quad fully in edge range
        int4 sv = *(const int4*)&ei[e0];
        int4 dv = *(const int4*)&ei[NE + e0];
        s[0] = sv.x; s[1] = sv.y; s[2] = sv.z; s[3] = sv.w;
        d[0] = dv.x; d[1] = dv.y; d[2] = dv.z; d[3] = dv.w;
    } else {         // quad fully self-loops
        #pragma unroll
        for (int j = 0; j < 4; j++) { s[j] = d[j] = e0 + j - NE; }
    }

    // 8 independent scattered loads in flight
    float4 as[4], ad[4];
    #pragma unroll
    for (int j = 0; j < 4; j++) {
        as[j] = *(const float4*)&g_as[s[j] * NH];
        ad[j] = *(const float4*)&g_ad[d[j] * NH];
    }

    #pragma unroll
    for (int j = 0; j < 4; j++) {
        float4 v;
        v.x = __expf(leaky(as[j].x + ad[j].x));
        v.y = __expf(leaky(as[j].y + ad[j].y));
        v.z = __expf(leaky(as[j].z + ad[j].z));
        v.w = __expf(leaky(as[j].w + ad[j].w));
        *(float4*)&g_ew[(size_t)(e0 + j) * NH] = v;
        float* dp = &g_den[d[j] * NH];
        asm volatile("red.global.add.v4.f32 [%0], {%1, %2, %3, %4};"
                     :: "l"(dp), "f"(v.x), "f"(v.y), "f"(v.z), "f"(v.w) : "memory");
    }
}

// ---------------- weighted scatter: 4 edges per warp, cached exps -------
__global__ __launch_bounds__(256) void k_scatter(const int* __restrict__ ei,
                                                 float* __restrict__ out) {
    int w    = (blockIdx.x * blockDim.x + threadIdx.x) >> 5;
    int lane = threadIdx.x & 31;
    if (w >= ETOT / 4) return;
    const int e0 = 4 * w;

    int s[4], d[4];
    #pragma unroll
    for (int j = 0; j < 4; j++) {
        int e = e0 + j;
        if (e < NE) { s[j] = __ldg(&ei[e]); d[j] = __ldg(&ei[NE + e]); }
        else        { s[j] = d[j] = e - NE; }
    }

    // lanes 0-15: weight = cached_exp / den  (coalesced 64B exp load)
    float wt = 0.f;
    if (lane < 16) {
        int j = lane >> 2, h = lane & 3;
        float ew = __ldg(&g_ew[(size_t)e0 * NH + lane]);
        wt = __fdividef(ew, g_den[d[j] * NH + h] + 1e-16f);
    }

    // 16 independent 256B warp-gathers in flight
    uint2 q[4][4];
    #pragma unroll
    for (int j = 0; j < 4; j++) {
        const uint2* xr = (const uint2*)(g_xlh + (size_t)s[j] * HC);
        q[j][0] = __ldg(&xr[lane]);
        q[j][1] = __ldg(&xr[32 + lane]);
        q[j][2] = __ldg(&xr[64 + lane]);
        q[j][3] = __ldg(&xr[96 + lane]);
    }

    #pragma unroll
    for (int j = 0; j < 4; j++) {
        float4 r = make_float4(0.f, 0.f, 0.f, 0.f);
        #pragma unroll
        for (int h = 0; h < 4; h++) {
            float wh = __shfl_sync(0xFFFFFFFFu, wt, j * 4 + h);
            float2 f0 = __half22float2(*(__half2*)&q[j][h].x);
            float2 f1 = __half22float2(*(__half2*)&q[j][h].y);
            r.x += wh * f0.x; r.y += wh * f0.y; r.z += wh * f1.x; r.w += wh * f1.y;
        }
        float* dp = out + (size_t)d[j] * OC + lane * 4;
        asm volatile("red.global.add.v4.f32 [%0], {%1, %2, %3, %4};"
                     :: "l"(dp), "f"(r.x), "f"(r.y), "f"(r.z), "f"(r.w) : "memory");
    }
}

// ---------------- finalize (float4) ----------------
__global__ void k_final(float* __restrict__ out, const float* __restrict__ bias) {
    int i = blockIdx.x * blockDim.x + threadIdx.x;
    if (i >= NN * OC / 4) return;
    float4 v = ((const float4*)out)[i];
    float4 b = ((const float4*)bias)[i & 31];
    v.x = v.x * 0.25f + b.x;
    v.y = v.y * 0.25f + b.y;
    v.z = v.z * 0.25f + b.z;
    v.w = v.w * 0.25f + b.w;
    v.x = v.x > 0.f ? v.x : __expf(v.x) - 1.f;
    v.y = v.y > 0.f ? v.y : __expf(v.y) - 1.f;
    v.z = v.z > 0.f ? v.z : __expf(v.z) - 1.f;
    v.w = v.w > 0.f ? v.w : __expf(v.w) - 1.f;
    ((float4*)out)[i] = v;
}

// ========================================================================
extern "C" void kernel_launch(void* const* d_in, const int* in_sizes, int n_in,
                              void* d_out, int out_size) {
    const float* x       = (const float*)d_in[0];
    const float* W       = (const float*)d_in[1];
    const float* att_src = (const float*)d_in[2];
    const float* att_dst = (const float*)d_in[3];
    const float* bias    = (const float*)d_in[4];
    const int*   ei      = (const int*)d_in[5];
    float* out = (float*)d_out;

    static cudaStream_t s_side = []() {
        cudaStream_t s; cudaStreamCreateWithFlags(&s, cudaStreamNonBlocking); return s;
    }();
    static cudaEvent_t ev_fork = []() {
        cudaEvent_t e; cudaEventCreateWithFlags(&e, cudaEventDisableTiming); return e;
    }();
    static cudaEvent_t ev_join = []() {
        cudaEvent_t e; cudaEventCreateWithFlags(&e, cudaEventDisableTiming); return e;
    }();
    static void* denp = []() { void* p; cudaGetSymbolAddress(&p, g_den); return p; }();

    cudaFuncSetAttribute(k_gemm_tc, cudaFuncAttributeMaxDynamicSharedMemorySize,
                         GEMM_SMEM);

    // fork: accumulator zeroing on copy engines (parallel to SM work)
    cudaEventRecord(ev_fork, 0);
    cudaStreamWaitEvent(s_side, ev_fork, 0);
    cudaMemsetAsync(out, 0, (size_t)NN * OC * sizeof(float), s_side);
    cudaMemsetAsync(denp, 0, (size_t)NN * NH * sizeof(float), s_side);
    cudaEventRecord(ev_join, s_side);

    // main stream: cvt + GEMM
    const int cvt_tot = (NN * KDIM + KDIM * NDIM) / 16;
    k_cvt<<<(cvt_tot + 255) / 256, 256>>>(x, W);

    dim3 ggrid(NDIM / 128, (NN + 127) / 128);   // (4, 157)
    k_gemm_tc<<<ggrid, 256, GEMM_SMEM>>>(att_src, att_dst);

    // join (zeroed buffers needed from here on)
    cudaStreamWaitEvent(0, ev_join, 0);
    k_edge_sum<<<(ETOT / 4 + 255) / 256, 256>>>(ei);
    k_scatter<<<(ETOT / 4 * 32 + 255) / 256, 256>>>(ei, out);
    k_final<<<(NN * OC / 4 + 255) / 256, 256>>>(out, bias);
}

// round 16
// speedup vs baseline: 1.0325x; 1.0325x over previous
#include <cuda_runtime.h>
#include <cuda_fp16.h>
#include <cfloat>
#include <math.h>
#include <cstdint>
#include <mma.h>

using namespace nvcuda;

// Problem constants
#define NN   20000
#define NE   320000
#define HC   512
#define NH   4
#define OC   128
#define KDIM 512
#define NDIM 512
#define ETOT (NE + NN)   // 340000 (divisible by 4; NE divisible by 4)

// -------- scratch --------
__device__ __half g_xh[(size_t)NN * KDIM];    // x, fp16
__device__ __half g_wh[(size_t)KDIM * NDIM];  // W, fp16
__device__ __half g_xlh[(size_t)NN * HC];     // projected features, fp16
__device__ __align__(16) float g_as[NN * NH];
__device__ __align__(16) float g_ad[NN * NH];
__device__ __align__(16) float g_den[NN * NH];
__device__ __align__(16) float g_ew[(size_t)ETOT * NH];  // cached exp per (edge, head)

// ---------------- fp16 pre-conversion of x and W (8 floats/thread) ------
__global__ void k_cvt(const float* __restrict__ x, const float* __restrict__ W) {
    const int totx8 = NN * KDIM / 8;
    const int totw8 = KDIM * NDIM / 8;
    int i = blockIdx.x * blockDim.x + threadIdx.x;
    const float4* src;
    uint4* dst;
    int j;
    if (i < totx8)              { src = (const float4*)x; dst = (uint4*)g_xh; j = i; }
    else if (i < totx8 + totw8) { src = (const float4*)W; dst = (uint4*)g_wh; j = i - totx8; }
    else return;
    float4 v0 = src[2 * j];
    float4 v1 = src[2 * j + 1];
    union { uint4 u; __half2 h[4]; } pk;
    pk.h[0] = __floats2half2_rn(v0.x, v0.y);
    pk.h[1] = __floats2half2_rn(v0.z, v0.w);
    pk.h[2] = __floats2half2_rn(v1.x, v1.y);
    pk.h[3] = __floats2half2_rn(v1.z, v1.w);
    dst[j] = pk.u;
}

// ---------------- GEMM (fp16 wmma 16x16x16) + fused epilogue -------------
#define BLK_K  64
#define LDA_H  72
#define LDB_H  136
#define A_HALFS (128 * LDA_H)
#define B_HALFS (BLK_K * LDB_H)
#define STAGE_HALFS (A_HALFS + B_HALFS)
#define NSTAGE 3
#define GEMM_SMEM (NSTAGE * STAGE_HALFS * 2)
#define LDC 132

__device__ __forceinline__ uint32_t smem_u32(const void* p) {
    uint32_t a;
    asm("{ .reg .u64 t; cvta.to.shared.u64 t, %1; cvt.u32.u64 %0, t; }" : "=r"(a) : "l"(p));
    return a;
}

__global__ __launch_bounds__(256) void k_gemm_tc(const float* __restrict__ att_src,
                                                 const float* __restrict__ att_dst) {
    extern __shared__ __half smemh[];
    __half* As = smemh;
    __half* Bs = smemh + NSTAGE * A_HALFS;

    const int tid = threadIdx.x;
    const int warpId = tid >> 5;
    const int lane = tid & 31;
    const int warpM = warpId & 3;
    const int warpN = warpId >> 2;
    const int m0 = blockIdx.y * 128;
    const int n0 = blockIdx.x * 128;

    const uint32_t sA = smem_u32(As);
    const uint32_t sB = smem_u32(Bs);

    auto load_stage = [&](int kc, int buf) {
        const int k0 = kc * BLK_K;
        #pragma unroll
        for (int it = 0; it < 4; it++) {
            int id = tid + it * 256;
            int r = id >> 3, q = id & 7;
            int grow = m0 + r;
            const __half* gp = g_xh + (size_t)(grow < NN ? grow : 0) * KDIM + k0 + q * 8;
            int sz = (grow < NN) ? 16 : 0;
            uint32_t so = sA + (buf * A_HALFS + r * LDA_H + q * 8) * 2;
            asm volatile("cp.async.cg.shared.global [%0], [%1], 16, %2;"
                         :: "r"(so), "l"(gp), "r"(sz));
        }
        #pragma unroll
        for (int it = 0; it < 4; it++) {
            int id = tid + it * 256;
            int r = id >> 4, q = id & 15;
            const __half* gp = g_wh + (size_t)(k0 + r) * NDIM + n0 + q * 8;
            uint32_t so = sB + (buf * B_HALFS + r * LDB_H + q * 8) * 2;
            asm volatile("cp.async.cg.shared.global [%0], [%1], 16;"
                         :: "r"(so), "l"(gp));
        }
        asm volatile("cp.async.commit_group;" ::: "memory");
    };

    wmma::fragment<wmma::accumulator, 16, 16, 16, float> acc[2][4];
    #pragma unroll
    for (int i = 0; i < 2; i++)
        #pragma unroll
        for (int j = 0; j < 4; j++) wmma::fill_fragment(acc[i][j], 0.f);

    load_stage(0, 0);
    load_stage(1, 1);

    const int NCHUNK = KDIM / BLK_K;   // 8
    for (int kc = 0; kc < NCHUNK; kc++) {
        const int buf = kc % NSTAGE;
        if (kc + 1 < NCHUNK)
            asm volatile("cp.async.wait_group 1;" ::: "memory");
        else
            asm volatile("cp.async.wait_group 0;" ::: "memory");
        __syncthreads();
        if (kc + 2 < NCHUNK) load_stage(kc + 2, (kc + 2) % NSTAGE);

        const __half* Ab = As + buf * A_HALFS + warpM * 32 * LDA_H;
        const __half* Bb = Bs + buf * B_HALFS + warpN * 64;
        #pragma unroll
        for (int ks = 0; ks < BLK_K / 16; ks++) {
            wmma::fragment<wmma::matrix_a, 16, 16, 16, __half, wmma::row_major> af[2];
            wmma::fragment<wmma::matrix_b, 16, 16, 16, __half, wmma::row_major> bf[4];
            #pragma unroll
            for (int mt = 0; mt < 2; mt++)
                wmma::load_matrix_sync(af[mt], Ab + mt * 16 * LDA_H + ks * 16, LDA_H);
            #pragma unroll
            for (int nt = 0; nt < 4; nt++)
                wmma::load_matrix_sync(bf[nt], Bb + ks * 16 * LDB_H + nt * 16, LDB_H);
            #pragma unroll
            for (int mt = 0; mt < 2; mt++)
                #pragma unroll
                for (int nt = 0; nt < 4; nt++)
                    wmma::mma_sync(acc[mt][nt], af[mt], bf[nt], acc[mt][nt]);
        }
    }

    // -------- fused epilogue: attn halves + fp16 store --------
    __syncthreads();
    float* Cs = (float*)smemh;
    #pragma unroll
    for (int mt = 0; mt < 2; mt++)
        #pragma unroll
        for (int nt = 0; nt < 4; nt++)
            wmma::store_matrix_sync(Cs + (warpM * 32 + mt * 16) * LDC + warpN * 64 + nt * 16,
                                    acc[mt][nt], LDC, wmma::mem_row_major);
    __syncthreads();

    const int h = blockIdx.x;
    float4 sv = *(const float4*)(att_src + h * OC + lane * 4);
    float4 dv = *(const float4*)(att_dst + h * OC + lane * 4);

    #pragma unroll
    for (int r = 0; r < 16; r++) {
        int lrow = warpId * 16 + r;
        int grow = m0 + lrow;
        float4 v = *(const float4*)(Cs + lrow * LDC + lane * 4);
        float ss = v.x * sv.x + v.y * sv.y + v.z * sv.z + v.w * sv.w;
        float dd = v.x * dv.x + v.y * dv.y + v.z * dv.z + v.w * dv.w;
        #pragma unroll
        for (int o = 16; o; o >>= 1) {
            ss += __shfl_xor_sync(0xFFFFFFFFu, ss, o);
            dd += __shfl_xor_sync(0xFFFFFFFFu, dd, o);
        }
        if (grow < NN) {
            union { uint2 u; __half2 hh[2]; } pk;
            pk.hh[0] = __floats2half2_rn(v.x, v.y);
            pk.hh[1] = __floats2half2_rn(v.z, v.w);
            *(uint2*)(g_xlh + (size_t)grow * HC + h * OC + lane * 4) = pk.u;
            if (lane == 0) {
                g_as[grow * NH + h] = ss;
                g_ad[grow * NH + h] = dd;
            }
        }
    }
}

__device__ __forceinline__ float leaky(float a) { return a > 0.f ? a : 0.2f * a; }

// ---------------- segment sum of exp: thread per edge, caches exps ------
__global__ void k_edge_sum(const int* __restrict__ ei) {
    int e = blockIdx.x * blockDim.x + threadIdx.x;
    if (e >= ETOT) return;
    int src, dst;
    if (e < NE) { src = __ldg(&ei[e]); dst = __ldg(&ei[NE + e]); }
    else        { src = dst = e - NE; }
    float4 as = *(const float4*)&g_as[src * NH];
    float4 ad = *(const float4*)&g_ad[dst * NH];
    float4 v;
    v.x = __expf(leaky(as.x + ad.x));
    v.y = __expf(leaky(as.y + ad.y));
    v.z = __expf(leaky(as.z + ad.z));
    v.w = __expf(leaky(as.w + ad.w));
    *(float4*)&g_ew[(size_t)e * NH] = v;   // cache for the scatter pass
    float* dp = &g_den[dst * NH];
    asm volatile("red.global.add.v4.f32 [%0], {%1, %2, %3, %4};"
                 :: "l"(dp), "f"(v.x), "f"(v.y), "f"(v.z), "f"(v.w) : "memory");
}

// ---------------- weighted scatter: 4 edges per warp, cached exps -------
__global__ __launch_bounds__(256) void k_scatter(const int* __restrict__ ei,
                                                 float* __restrict__ out) {
    int w    = (blockIdx.x * blockDim.x + threadIdx.x) >> 5;
    int lane = threadIdx.x & 31;
    if (w >= ETOT / 4) return;
    const int e0 = 4 * w;

    // NE % 4 == 0 and e0 % 4 == 0: quad is all-real or all-self-loop
    int s[4], d[4];
    if (e0 < NE) {
        int4 sv = *(const int4*)&ei[e0];
        int4 dv = *(const int4*)&ei[NE + e0];
        s[0] = sv.x; s[1] = sv.y; s[2] = sv.z; s[3] = sv.w;
        d[0] = dv.x; d[1] = dv.y; d[2] = dv.z; d[3] = dv.w;
    } else {
        #pragma unroll
        for (int j = 0; j < 4; j++) { s[j] = d[j] = e0 + j - NE; }
    }

    // lanes 0-15: weight = cached_exp / den  (coalesced 64B exp load)
    float wt = 0.f;
    if (lane < 16) {
        int j = lane >> 2, h = lane & 3;
        float ew = __ldg(&g_ew[(size_t)e0 * NH + lane]);
        wt = __fdividef(ew, g_den[d[j] * NH + h] + 1e-16f);
    }

    // 16 independent 256B warp-gathers in flight
    uint2 q[4][4];
    #pragma unroll
    for (int j = 0; j < 4; j++) {
        const uint2* xr = (const uint2*)(g_xlh + (size_t)s[j] * HC);
        q[j][0] = __ldg(&xr[lane]);
        q[j][1] = __ldg(&xr[32 + lane]);
        q[j][2] = __ldg(&xr[64 + lane]);
        q[j][3] = __ldg(&xr[96 + lane]);
    }

    #pragma unroll
    for (int j = 0; j < 4; j++) {
        float4 r = make_float4(0.f, 0.f, 0.f, 0.f);
        #pragma unroll
        for (int h = 0; h < 4; h++) {
            float wh = __shfl_sync(0xFFFFFFFFu, wt, j * 4 + h);
            float2 f0 = __half22float2(*(__half2*)&q[j][h].x);
            float2 f1 = __half22float2(*(__half2*)&q[j][h].y);
            r.x += wh * f0.x; r.y += wh * f0.y; r.z += wh * f1.x; r.w += wh * f1.y;
        }
        float* dp = out + (size_t)d[j] * OC + lane * 4;
        asm volatile("red.global.add.v4.f32 [%0], {%1, %2, %3, %4};"
                     :: "l"(dp), "f"(r.x), "f"(r.y), "f"(r.z), "f"(r.w) : "memory");
    }
}

// ---------------- finalize (float4) ----------------
__global__ void k_final(float* __restrict__ out, const float* __restrict__ bias) {
    int i = blockIdx.x * blockDim.x + threadIdx.x;
    if (i >= NN * OC / 4) return;
    float4 v = ((const float4*)out)[i];
    float4 b = ((const float4*)bias)[i & 31];
    v.x = v.x * 0.25f + b.x;
    v.y = v.y * 0.25f + b.y;
    v.z = v.z * 0.25f + b.z;
    v.w = v.w * 0.25f + b.w;
    v.x = v.x > 0.f ? v.x : __expf(v.x) - 1.f;
    v.y = v.y > 0.f ? v.y : __expf(v.y) - 1.f;
    v.z = v.z > 0.f ? v.z : __expf(v.z) - 1.f;
    v.w = v.w > 0.f ? v.w : __expf(v.w) - 1.f;
    ((float4*)out)[i] = v;
}

// ========================================================================
extern "C" void kernel_launch(void* const* d_in, const int* in_sizes, int n_in,
                              void* d_out, int out_size) {
    const float* x       = (const float*)d_in[0];
    const float* W       = (const float*)d_in[1];
    const float* att_src = (const float*)d_in[2];
    const float* att_dst = (const float*)d_in[3];
    const float* bias    = (const float*)d_in[4];
    const int*   ei      = (const int*)d_in[5];
    float* out = (float*)d_out;

    static cudaStream_t s_side = []() {
        cudaStream_t s; cudaStreamCreateWithFlags(&s, cudaStreamNonBlocking); return s;
    }();
    static cudaEvent_t ev_fork = []() {
        cudaEvent_t e; cudaEventCreateWithFlags(&e, cudaEventDisableTiming); return e;
    }();
    static cudaEvent_t ev_join = []() {
        cudaEvent_t e; cudaEventCreateWithFlags(&e, cudaEventDisableTiming); return e;
    }();
    static void* denp = []() { void* p; cudaGetSymbolAddress(&p, g_den); return p; }();

    cudaFuncSetAttribute(k_gemm_tc, cudaFuncAttributeMaxDynamicSharedMemorySize,
                         GEMM_SMEM);

    // fork: accumulator zeroing on copy engines (parallel to SM work)
    cudaEventRecord(ev_fork, 0);
    cudaStreamWaitEvent(s_side, ev_fork, 0);
    cudaMemsetAsync(out, 0, (size_t)NN * OC * sizeof(float), s_side);
    cudaMemsetAsync(denp, 0, (size_t)NN * NH * sizeof(float), s_side);
    cudaEventRecord(ev_join, s_side);

    // main stream: cvt + GEMM
    const int cvt_tot = (NN * KDIM + KDIM * NDIM) / 8;
    k_cvt<<<(cvt_tot + 255) / 256, 256>>>(x, W);

    dim3 ggrid(NDIM / 128, (NN + 127) / 128);   // (4, 157)
    k_gemm_tc<<<ggrid, 256, GEMM_SMEM>>>(att_src, att_dst);

    // join (zeroed buffers needed from here on)
    cudaStreamWaitEvent(0, ev_join, 0);
    k_edge_sum<<<(ETOT + 255) / 256, 256>>>(ei);
    k_scatter<<<(ETOT / 4 * 32 + 255) / 256, 256>>>(ei, out);
    k_final<<<(NN * OC / 4 + 255) / 256, 256>>>(out, bias);
}

// round 17
// speedup vs baseline: 1.0631x; 1.0296x over previous
#include <cuda_runtime.h>
#include <cuda_fp16.h>
#include <cfloat>
#include <math.h>
#include <cstdint>
#include <mma.h>

using namespace nvcuda;

// Problem constants
#define NN   20000
#define NE   320000
#define HC   512
#define NH   4
#define OC   128
#define KDIM 512
#define NDIM 512
#define ETOT (NE + NN)   // 340000 (divisible by 4; NE divisible by 4)

// -------- scratch --------
__device__ __half g_xh[(size_t)NN * KDIM];    // x, fp16
__device__ __half g_wh[(size_t)KDIM * NDIM];  // W, fp16
__device__ __half g_xlh[(size_t)NN * HC];     // projected features, fp16
__device__ __align__(16) float g_as[NN * NH];
__device__ __align__(16) float g_ad[NN * NH];
__device__ __align__(16) float g_den[NN * NH];
__device__ __align__(16) float g_ew[(size_t)ETOT * NH];  // cached exp per (edge, head)

// ---------------- fp16 pre-conversion of x and W + g_den zeroing --------
__global__ void k_cvt(const float* __restrict__ x, const float* __restrict__ W) {
    const int totx8 = NN * KDIM / 8;
    const int totw8 = KDIM * NDIM / 8;
    int i = blockIdx.x * blockDim.x + threadIdx.x;
    if (i < NN)   // fold the g_den zeroing into this kernel (one float4/node)
        ((float4*)g_den)[i] = make_float4(0.f, 0.f, 0.f, 0.f);
    const float4* src;
    uint4* dst;
    int j;
    if (i < totx8)              { src = (const float4*)x; dst = (uint4*)g_xh; j = i; }
    else if (i < totx8 + totw8) { src = (const float4*)W; dst = (uint4*)g_wh; j = i - totx8; }
    else return;
    float4 v0 = src[2 * j];
    float4 v1 = src[2 * j + 1];
    union { uint4 u; __half2 h[4]; } pk;
    pk.h[0] = __floats2half2_rn(v0.x, v0.y);
    pk.h[1] = __floats2half2_rn(v0.z, v0.w);
    pk.h[2] = __floats2half2_rn(v1.x, v1.y);
    pk.h[3] = __floats2half2_rn(v1.z, v1.w);
    dst[j] = pk.u;
}

// ---------------- GEMM (fp16 wmma 16x16x16) + fused epilogue -------------
#define BLK_K  64
#define LDA_H  72
#define LDB_H  136
#define A_HALFS (128 * LDA_H)
#define B_HALFS (BLK_K * LDB_H)
#define STAGE_HALFS (A_HALFS + B_HALFS)
#define NSTAGE 3
#define GEMM_SMEM (NSTAGE * STAGE_HALFS * 2)
#define LDC 132

__device__ __forceinline__ uint32_t smem_u32(const void* p) {
    uint32_t a;
    asm("{ .reg .u64 t; cvta.to.shared.u64 t, %1; cvt.u32.u64 %0, t; }" : "=r"(a) : "l"(p));
    return a;
}

__global__ __launch_bounds__(256) void k_gemm_tc(const float* __restrict__ att_src,
                                                 const float* __restrict__ att_dst,
                                                 float* __restrict__ out) {
    extern __shared__ __half smemh[];
    __half* As = smemh;
    __half* Bs = smemh + NSTAGE * A_HALFS;

    const int tid = threadIdx.x;
    const int warpId = tid >> 5;
    const int lane = tid & 31;
    const int warpM = warpId & 3;
    const int warpN = warpId >> 2;
    const int m0 = blockIdx.y * 128;
    const int n0 = blockIdx.x * 128;

    const uint32_t sA = smem_u32(As);
    const uint32_t sB = smem_u32(Bs);

    auto load_stage = [&](int kc, int buf) {
        const int k0 = kc * BLK_K;
        #pragma unroll
        for (int it = 0; it < 4; it++) {
            int id = tid + it * 256;
            int r = id >> 3, q = id & 7;
            int grow = m0 + r;
            const __half* gp = g_xh + (size_t)(grow < NN ? grow : 0) * KDIM + k0 + q * 8;
            int sz = (grow < NN) ? 16 : 0;
            uint32_t so = sA + (buf * A_HALFS + r * LDA_H + q * 8) * 2;
            asm volatile("cp.async.cg.shared.global [%0], [%1], 16, %2;"
                         :: "r"(so), "l"(gp), "r"(sz));
        }
        #pragma unroll
        for (int it = 0; it < 4; it++) {
            int id = tid + it * 256;
            int r = id >> 4, q = id & 15;
            const __half* gp = g_wh + (size_t)(k0 + r) * NDIM + n0 + q * 8;
            uint32_t so = sB + (buf * B_HALFS + r * LDB_H + q * 8) * 2;
            asm volatile("cp.async.cg.shared.global [%0], [%1], 16;"
                         :: "r"(so), "l"(gp));
        }
        asm volatile("cp.async.commit_group;" ::: "memory");
    };

    wmma::fragment<wmma::accumulator, 16, 16, 16, float> acc[2][4];
    #pragma unroll
    for (int i = 0; i < 2; i++)
        #pragma unroll
        for (int j = 0; j < 4; j++) wmma::fill_fragment(acc[i][j], 0.f);

    load_stage(0, 0);
    load_stage(1, 1);

    const int NCHUNK = KDIM / BLK_K;   // 8
    for (int kc = 0; kc < NCHUNK; kc++) {
        const int buf = kc % NSTAGE;
        if (kc + 1 < NCHUNK)
            asm volatile("cp.async.wait_group 1;" ::: "memory");
        else
            asm volatile("cp.async.wait_group 0;" ::: "memory");
        __syncthreads();
        if (kc + 2 < NCHUNK) load_stage(kc + 2, (kc + 2) % NSTAGE);

        const __half* Ab = As + buf * A_HALFS + warpM * 32 * LDA_H;
        const __half* Bb = Bs + buf * B_HALFS + warpN * 64;
        #pragma unroll
        for (int ks = 0; ks < BLK_K / 16; ks++) {
            wmma::fragment<wmma::matrix_a, 16, 16, 16, __half, wmma::row_major> af[2];
            wmma::fragment<wmma::matrix_b, 16, 16, 16, __half, wmma::row_major> bf[4];
            #pragma unroll
            for (int mt = 0; mt < 2; mt++)
                wmma::load_matrix_sync(af[mt], Ab + mt * 16 * LDA_H + ks * 16, LDA_H);
            #pragma unroll
            for (int nt = 0; nt < 4; nt++)
                wmma::load_matrix_sync(bf[nt], Bb + ks * 16 * LDB_H + nt * 16, LDB_H);
            #pragma unroll
            for (int mt = 0; mt < 2; mt++)
                #pragma unroll
                for (int nt = 0; nt < 4; nt++)
                    wmma::mma_sync(acc[mt][nt], af[mt], bf[nt], acc[mt][nt]);
        }
    }

    // -------- fused epilogue: attn halves + fp16 store + out zeroing ----
    __syncthreads();
    float* Cs = (float*)smemh;
    #pragma unroll
    for (int mt = 0; mt < 2; mt++)
        #pragma unroll
        for (int nt = 0; nt < 4; nt++)
            wmma::store_matrix_sync(Cs + (warpM * 32 + mt * 16) * LDC + warpN * 64 + nt * 16,
                                    acc[mt][nt], LDC, wmma::mem_row_major);
    __syncthreads();

    const int h = blockIdx.x;

    // h==0 CTAs zero this M-block's rows of out (replaces cudaMemsetAsync)
    if (h == 0) {
        const float4 z = make_float4(0.f, 0.f, 0.f, 0.f);
        for (int idx = tid; idx < 128 * 32; idx += 256) {
            int row = m0 + (idx >> 5);
            if (row < NN)
                ((float4*)(out + (size_t)row * OC))[idx & 31] = z;
        }
    }

    float4 sv = *(const float4*)(att_src + h * OC + lane * 4);
    float4 dv = *(const float4*)(att_dst + h * OC + lane * 4);

    #pragma unroll
    for (int r = 0; r < 16; r++) {
        int lrow = warpId * 16 + r;
        int grow = m0 + lrow;
        float4 v = *(const float4*)(Cs + lrow * LDC + lane * 4);
        float ss = v.x * sv.x + v.y * sv.y + v.z * sv.z + v.w * sv.w;
        float dd = v.x * dv.x + v.y * dv.y + v.z * dv.z + v.w * dv.w;
        #pragma unroll
        for (int o = 16; o; o >>= 1) {
            ss += __shfl_xor_sync(0xFFFFFFFFu, ss, o);
            dd += __shfl_xor_sync(0xFFFFFFFFu, dd, o);
        }
        if (grow < NN) {
            union { uint2 u; __half2 hh[2]; } pk;
            pk.hh[0] = __floats2half2_rn(v.x, v.y);
            pk.hh[1] = __floats2half2_rn(v.z, v.w);
            *(uint2*)(g_xlh + (size_t)grow * HC + h * OC + lane * 4) = pk.u;
            if (lane == 0) {
                g_as[grow * NH + h] = ss;
                g_ad[grow * NH + h] = dd;
            }
        }
    }
}

__device__ __forceinline__ float leaky(float a) { return a > 0.f ? a : 0.2f * a; }

// ---------------- segment sum of exp: thread per edge, caches exps ------
__global__ void k_edge_sum(const int* __restrict__ ei) {
    int e = blockIdx.x * blockDim.x + threadIdx.x;
    if (e >= ETOT) return;
    int src, dst;
    if (e < NE) { src = __ldg(&ei[e]); dst = __ldg(&ei[NE + e]); }
    else        { src = dst = e - NE; }
    float4 as = *(const float4*)&g_as[src * NH];
    float4 ad = *(const float4*)&g_ad[dst * NH];
    float4 v;
    v.x = __expf(leaky(as.x + ad.x));
    v.y = __expf(leaky(as.y + ad.y));
    v.z = __expf(leaky(as.z + ad.z));
    v.w = __expf(leaky(as.w + ad.w));
    *(float4*)&g_ew[(size_t)e * NH] = v;   // cache for the scatter pass
    float* dp = &g_den[dst * NH];
    asm volatile("red.global.add.v4.f32 [%0], {%1, %2, %3, %4};"
                 :: "l"(dp), "f"(v.x), "f"(v.y), "f"(v.z), "f"(v.w) : "memory");
}

// ---------------- weighted scatter: 4 edges per warp, cached exps -------
__global__ __launch_bounds__(256) void k_scatter(const int* __restrict__ ei,
                                                 float* __restrict__ out) {
    int w    = (blockIdx.x * blockDim.x + threadIdx.x) >> 5;
    int lane = threadIdx.x & 31;
    if (w >= ETOT / 4) return;
    const int e0 = 4 * w;

    // NE % 4 == 0 and e0 % 4 == 0: quad is all-real or all-self-loop
    int s[4], d[4];
    if (e0 < NE) {
        int4 sv = *(const int4*)&ei[e0];
        int4 dv = *(const int4*)&ei[NE + e0];
        s[0] = sv.x; s[1] = sv.y; s[2] = sv.z; s[3] = sv.w;
        d[0] = dv.x; d[1] = dv.y; d[2] = dv.z; d[3] = dv.w;
    } else {
        #pragma unroll
        for (int j = 0; j < 4; j++) { s[j] = d[j] = e0 + j - NE; }
    }

    // lanes 0-15: weight = cached_exp / den  (coalesced 64B exp load)
    float wt = 0.f;
    if (lane < 16) {
        int j = lane >> 2, h = lane & 3;
        float ew = __ldg(&g_ew[(size_t)e0 * NH + lane]);
        wt = __fdividef(ew, g_den[d[j] * NH + h] + 1e-16f);
    }

    // 16 independent 256B warp-gathers in flight
    uint2 q[4][4];
    #pragma unroll
    for (int j = 0; j < 4; j++) {
        const uint2* xr = (const uint2*)(g_xlh + (size_t)s[j] * HC);
        q[j][0] = __ldg(&xr[lane]);
        q[j][1] = __ldg(&xr[32 + lane]);
        q[j][2] = __ldg(&xr[64 + lane]);
        q[j][3] = __ldg(&xr[96 + lane]);
    }

    #pragma unroll
    for (int j = 0; j < 4; j++) {
        float4 r = make_float4(0.f, 0.f, 0.f, 0.f);
        #pragma unroll
        for (int h = 0; h < 4; h++) {
            float wh = __shfl_sync(0xFFFFFFFFu, wt, j * 4 + h);
            float2 f0 = __half22float2(*(__half2*)&q[j][h].x);
            float2 f1 = __half22float2(*(__half2*)&q[j][h].y);
            r.x += wh * f0.x; r.y += wh * f0.y; r.z += wh * f1.x; r.w += wh * f1.y;
        }
        float* dp = out + (size_t)d[j] * OC + lane * 4;
        asm volatile("red.global.add.v4.f32 [%0], {%1, %2, %3, %4};"
                     :: "l"(dp), "f"(r.x), "f"(r.y), "f"(r.z), "f"(r.w) : "memory");
    }
}

// ---------------- finalize (float4) ----------------
__global__ void k_final(float* __restrict__ out, const float* __restrict__ bias) {
    int i = blockIdx.x * blockDim.x + threadIdx.x;
    if (i >= NN * OC / 4) return;
    float4 v = ((const float4*)out)[i];
    float4 b = ((const float4*)bias)[i & 31];
    v.x = v.x * 0.25f + b.x;
    v.y = v.y * 0.25f + b.y;
    v.z = v.z * 0.25f + b.z;
    v.w = v.w * 0.25f + b.w;
    v.x = v.x > 0.f ? v.x : __expf(v.x) - 1.f;
    v.y = v.y > 0.f ? v.y : __expf(v.y) - 1.f;
    v.z = v.z > 0.f ? v.z : __expf(v.z) - 1.f;
    v.w = v.w > 0.f ? v.w : __expf(v.w) - 1.f;
    ((float4*)out)[i] = v;
}

// ========================================================================
extern "C" void kernel_launch(void* const* d_in, const int* in_sizes, int n_in,
                              void* d_out, int out_size) {
    const float* x       = (const float*)d_in[0];
    const float* W       = (const float*)d_in[1];
    const float* att_src = (const float*)d_in[2];
    const float* att_dst = (const float*)d_in[3];
    const float* bias    = (const float*)d_in[4];
    const int*   ei      = (const int*)d_in[5];
    float* out = (float*)d_out;

    cudaFuncSetAttribute(k_gemm_tc, cudaFuncAttributeMaxDynamicSharedMemorySize,
                         GEMM_SMEM);

    // straight 5-kernel chain: no memsets, no side stream, no events
    const int cvt_tot = (NN * KDIM + KDIM * NDIM) / 8;
    k_cvt<<<(cvt_tot + 255) / 256, 256>>>(x, W);

    dim3 ggrid(NDIM / 128, (NN + 127) / 128);   // (4, 157)
    k_gemm_tc<<<ggrid, 256, GEMM_SMEM>>>(att_src, att_dst, out);

    k_edge_sum<<<(ETOT + 255) / 256, 256>>>(ei);
    k_scatter<<<(ETOT / 4 * 32 + 255) / 256, 256>>>(ei, out);
    k_final<<<(NN * OC / 4 + 255) / 256, 256>>>(out, bias);
}